// round 7
// baseline (speedup 1.0000x reference)
#include <cuda_runtime.h>
#include <cstdint>

#define NN    100000
#define EE    1600000
#define HIDD  128
#define INDIM 64
#define NBATCH 8
#define KTOP  5000
#define NPER  12500
#define NCLS  18
#define SORTN 16384
#define SCAN_BLOCKS 98   // ceil(100000 / 1024)

// packed fp32x2 helpers (sm_103a FFMA2 path; per-lane rn rounding == scalar FFMA)
#define PACKDUP(d, x)      asm("mov.b64 %0, {%1, %1};" : "=l"(d) : "f"(x))
#define FMA2(acc, a, b)    asm("fma.rn.f32x2 %0, %1, %2, %0;" : "+l"(acc) : "l"(a), "l"(b))
#define UNPACK2(lo, hi, v) asm("mov.b64 {%0, %1}, %2;" : "=f"(lo), "=f"(hi) : "l"(v))

// ---------------- scratch (device globals; referenced ONLY from device code) --
__device__ float g_t[(size_t)NN * HIDD];        // transformed feats (layer-1 scaled / layer-2 xW)
__device__ float g_h[(size_t)NN * HIDD];        // layer output features
__device__ float g_agg[(size_t)NN * INDIM];     // layer-1 aggregated scaled features
__device__ float g_norm_src[NN];
__device__ float g_norm_dst[NN];
__device__ int   g_deg_out[NN];
__device__ int   g_deg_in[NN];
__device__ int   g_row_start[NN + 1];
__device__ int   g_cursor[NN];
__device__ int   g_csr_src[EE];
__device__ int   g_topk[NBATCH * KTOP];
__device__ int   g_block_sums[SCAN_BLOCKS];
__device__ int   g_block_offs[SCAN_BLOCKS];

// ---------------- degree ------------------------------------------------------
__global__ void degree_kernel(const int* __restrict__ src, const int* __restrict__ dst) {
    int e = blockIdx.x * blockDim.x + threadIdx.x;
    if (e < EE) {
        atomicAdd(&g_deg_out[src[e]], 1);
        atomicAdd(&g_deg_in[dst[e]], 1);
    }
}

// ---------------- 3-phase multi-block exclusive scan of g_deg_in --------------
__global__ void scan_block_sum_kernel() {
    __shared__ int sh[1024];
    int tid = threadIdx.x;
    int i = blockIdx.x * 1024 + tid;
    int v = (i < NN) ? g_deg_in[i] : 0;
    sh[tid] = v;
    __syncthreads();
    #pragma unroll
    for (int off = 512; off > 0; off >>= 1) {
        if (tid < off) sh[tid] += sh[tid + off];
        __syncthreads();
    }
    if (tid == 0) g_block_sums[blockIdx.x] = sh[0];
}

__global__ void scan_partials_kernel() {
    if (threadIdx.x == 0) {
        int run = 0;
        for (int b = 0; b < SCAN_BLOCKS; b++) {
            g_block_offs[b] = run;
            run += g_block_sums[b];
        }
        g_row_start[NN] = run;
    }
}

// local scan + row_start/cursor + FUSED norm computation
__global__ void scan_local_kernel() {
    __shared__ int sh[1024];
    int tid = threadIdx.x;
    int i = blockIdx.x * 1024 + tid;
    int v = (i < NN) ? g_deg_in[i] : 0;
    sh[tid] = v;
    __syncthreads();
    #pragma unroll
    for (int off = 1; off < 1024; off <<= 1) {
        int add = (tid >= off) ? sh[tid - off] : 0;
        __syncthreads();
        sh[tid] += add;
        __syncthreads();
    }
    if (i < NN) {
        int excl = g_block_offs[blockIdx.x] + sh[tid] - v;
        g_row_start[i] = excl;
        g_cursor[i] = excl;
        g_norm_dst[i] = rsqrtf((float)max(v, 1));
        g_norm_src[i] = rsqrtf((float)max(g_deg_out[i], 1));
    }
}

__global__ void csr_fill_kernel(const int* __restrict__ src, const int* __restrict__ dst) {
    int e = blockIdx.x * blockDim.x + threadIdx.x;
    if (e < EE) {
        int d = dst[e];
        int pos = atomicAdd(&g_cursor[d], 1);
        g_csr_src[pos] = src[e];
    }
}

// ---------------- layer 1 front: g_t[n] = x[n] * norm_src[n] (64-dim) ---------
__global__ void scale_src_kernel(const float* __restrict__ x) {
    int i = blockIdx.x * blockDim.x + threadIdx.x;  // float4 index
    if (i < NN * INDIM / 4) {
        int node = i >> 4;                          // 16 float4 per 64-float row
        float ns = g_norm_src[node];
        float4 v = *(const float4*)&x[i * 4];
        v.x *= ns; v.y *= ns; v.z *= ns; v.w *= ns;
        *(float4*)&g_t[i * 4] = v;
    }
}

// ---------------- 64-dim aggregate: g_agg[n] = sum_{e:dst=n} g_t[src_e] -------
__global__ void aggregate64_kernel() {
    int gtid = blockIdx.x * blockDim.x + threadIdx.x;
    int node = gtid >> 5;
    int lane = gtid & 31;
    if (node >= NN) return;
    int s0 = g_row_start[node], s1 = g_row_start[node + 1];
    float2 acc0 = make_float2(0.f, 0.f);
    float2 acc1 = make_float2(0.f, 0.f);
    const float* tbase = (const float*)g_t;
    for (int base = s0; base < s1; base += 32) {
        int my = (base + lane < s1) ? g_csr_src[base + lane] : 0;
        int cnt = min(32, s1 - base);
        int t = 0;
        for (; t + 4 <= cnt; t += 4) {
            int sA = __shfl_sync(0xffffffffu, my, t);
            int sB = __shfl_sync(0xffffffffu, my, t + 1);
            int sC = __shfl_sync(0xffffffffu, my, t + 2);
            int sD = __shfl_sync(0xffffffffu, my, t + 3);
            float2 vA = *(const float2*)&tbase[(size_t)sA * 64 + lane * 2];
            float2 vB = *(const float2*)&tbase[(size_t)sB * 64 + lane * 2];
            float2 vC = *(const float2*)&tbase[(size_t)sC * 64 + lane * 2];
            float2 vD = *(const float2*)&tbase[(size_t)sD * 64 + lane * 2];
            acc0.x += vA.x; acc0.y += vA.y;
            acc1.x += vB.x; acc1.y += vB.y;
            acc0.x += vC.x; acc0.y += vC.y;
            acc1.x += vD.x; acc1.y += vD.y;
        }
        for (; t < cnt; t++) {
            int s = __shfl_sync(0xffffffffu, my, t);
            float2 v = *(const float2*)&tbase[(size_t)s * 64 + lane * 2];
            acc0.x += v.x; acc0.y += v.y;
        }
    }
    *(float2*)&g_agg[(size_t)node * 64 + lane * 2] =
        make_float2(acc0.x + acc1.x, acc0.y + acc1.y);
}

// ---------------- transform: 4 nodes x 4 cols per thread, f32x2 FMA ----------
// blockDim (32,8): 32 nodes/block, 128 cols.
// SRC 0: read g_agg (KD=64).  SRC 1: read g_h (KD=128).
// EPI 0: out = relu(acc*norm_dst + b) -> g_h.  EPI 1: out = acc*norm_src -> g_t.
template <int KD, int SRC, int EPI>
__global__ void __launch_bounds__(256)
transform_kernel(const float* __restrict__ W, const float* __restrict__ bias) {
    extern __shared__ float sh[];
    float* Ws = sh;                  // KD*128
    float* xs = sh + KD * 128;       // 32*KD
    int tx = threadIdx.x, ty = threadIdx.y;
    int tid = ty * 32 + tx;          // 0..255
    for (int i = tid * 4; i < KD * 128; i += 256 * 4)
        *(float4*)&Ws[i] = *(const float4*)&W[i];
    int base = blockIdx.x * 32;
    const float* xin = (SRC == 0) ? (const float*)g_agg : (const float*)g_h;
    for (int i = tid * 4; i < 32 * KD; i += 256 * 4)
        *(float4*)&xs[i] = *(const float4*)&xin[(size_t)base * KD + i];
    __syncthreads();

    unsigned long long a00 = 0, a01 = 0, a10 = 0, a11 = 0;
    unsigned long long a20 = 0, a21 = 0, a30 = 0, a31 = 0;
    const float* x0p = &xs[(ty * 4 + 0) * KD];
    const float* x1p = &xs[(ty * 4 + 1) * KD];
    const float* x2p = &xs[(ty * 4 + 2) * KD];
    const float* x3p = &xs[(ty * 4 + 3) * KD];
    #pragma unroll 4
    for (int k = 0; k < KD; k++) {
        ulonglong2 w = *(const ulonglong2*)&Ws[k * 128 + tx * 4];
        unsigned long long x0d, x1d, x2d, x3d;
        PACKDUP(x0d, x0p[k]); PACKDUP(x1d, x1p[k]);
        PACKDUP(x2d, x2p[k]); PACKDUP(x3d, x3p[k]);
        FMA2(a00, x0d, w.x); FMA2(a01, x0d, w.y);
        FMA2(a10, x1d, w.x); FMA2(a11, x1d, w.y);
        FMA2(a20, x2d, w.x); FMA2(a21, x2d, w.y);
        FMA2(a30, x3d, w.x); FMA2(a31, x3d, w.y);
    }

    float4 accs[4];
    UNPACK2(accs[0].x, accs[0].y, a00); UNPACK2(accs[0].z, accs[0].w, a01);
    UNPACK2(accs[1].x, accs[1].y, a10); UNPACK2(accs[1].z, accs[1].w, a11);
    UNPACK2(accs[2].x, accs[2].y, a20); UNPACK2(accs[2].z, accs[2].w, a21);
    UNPACK2(accs[3].x, accs[3].y, a30); UNPACK2(accs[3].z, accs[3].w, a31);

    int n0 = base + ty * 4;
    if (EPI == 0) {
        float4 b = *(const float4*)&bias[tx * 4];
        #pragma unroll
        for (int i = 0; i < 4; i++) {
            float nd = g_norm_dst[n0 + i];
            float4 a = accs[i];
            float4 r;
            r.x = fmaxf(a.x * nd + b.x, 0.f);
            r.y = fmaxf(a.y * nd + b.y, 0.f);
            r.z = fmaxf(a.z * nd + b.z, 0.f);
            r.w = fmaxf(a.w * nd + b.w, 0.f);
            *(float4*)&g_h[(size_t)(n0 + i) * 128 + tx * 4] = r;
        }
    } else {
        #pragma unroll
        for (int i = 0; i < 4; i++) {
            float ns = g_norm_src[n0 + i];
            float4 a = accs[i];
            a.x *= ns; a.y *= ns; a.z *= ns; a.w *= ns;
            *(float4*)&g_t[(size_t)(n0 + i) * 128 + tx * 4] = a;
        }
    }
}

// ---------------- 128-dim aggregate (layer 2) ---------------------------------
__global__ void aggregate_kernel(const float* __restrict__ bias) {
    int gtid = blockIdx.x * blockDim.x + threadIdx.x;
    int node = gtid >> 5;
    int lane = gtid & 31;
    if (node >= NN) return;
    int s0 = g_row_start[node], s1 = g_row_start[node + 1];
    float4 acc0 = make_float4(0.f, 0.f, 0.f, 0.f);
    float4 acc1 = make_float4(0.f, 0.f, 0.f, 0.f);
    const float* tbase = (const float*)g_t;
    for (int base = s0; base < s1; base += 32) {
        int my = (base + lane < s1) ? g_csr_src[base + lane] : 0;
        int cnt = min(32, s1 - base);
        int t = 0;
        for (; t + 4 <= cnt; t += 4) {
            int sA = __shfl_sync(0xffffffffu, my, t);
            int sB = __shfl_sync(0xffffffffu, my, t + 1);
            int sC = __shfl_sync(0xffffffffu, my, t + 2);
            int sD = __shfl_sync(0xffffffffu, my, t + 3);
            float4 vA = *(const float4*)&tbase[(size_t)sA * 128 + lane * 4];
            float4 vB = *(const float4*)&tbase[(size_t)sB * 128 + lane * 4];
            float4 vC = *(const float4*)&tbase[(size_t)sC * 128 + lane * 4];
            float4 vD = *(const float4*)&tbase[(size_t)sD * 128 + lane * 4];
            acc0.x += vA.x; acc0.y += vA.y; acc0.z += vA.z; acc0.w += vA.w;
            acc1.x += vB.x; acc1.y += vB.y; acc1.z += vB.z; acc1.w += vB.w;
            acc0.x += vC.x; acc0.y += vC.y; acc0.z += vC.z; acc0.w += vC.w;
            acc1.x += vD.x; acc1.y += vD.y; acc1.z += vD.z; acc1.w += vD.w;
        }
        for (; t < cnt; t++) {
            int s = __shfl_sync(0xffffffffu, my, t);
            float4 v = *(const float4*)&tbase[(size_t)s * 128 + lane * 4];
            acc0.x += v.x; acc0.y += v.y; acc0.z += v.z; acc0.w += v.w;
        }
    }
    float nd = g_norm_dst[node];
    float4 b = *(const float4*)&bias[lane * 4];
    float4 r;
    r.x = fmaxf((acc0.x + acc1.x) * nd + b.x, 0.f);
    r.y = fmaxf((acc0.y + acc1.y) * nd + b.y, 0.f);
    r.z = fmaxf((acc0.z + acc1.z) * nd + b.z, 0.f);
    r.w = fmaxf((acc0.w + acc1.w) * nd + b.w, 0.f);
    *(float4*)&g_h[(size_t)node * 128 + lane * 4] = r;
}

// ---------------- top-K + fused out init --------------------------------------
__global__ void topk_kernel(const float* __restrict__ b3, float* __restrict__ out) {
    extern __shared__ unsigned long long s[];
    int b = blockIdx.x;
    if (b == 0 && threadIdx.x < NBATCH * NCLS)
        out[threadIdx.x] = b3[threadIdx.x % NCLS];
    for (int i = threadIdx.x; i < SORTN; i += blockDim.x) {
        unsigned long long key;
        if (i < NPER) {
            float f = g_h[((size_t)(b * NPER + i)) * 128 + 127];
            unsigned bits = __float_as_uint(f);
            unsigned m = ((int)bits < 0) ? ~bits : (bits ^ 0x80000000u);
            key = (((unsigned long long)(~m)) << 32) | (unsigned)i;
        } else {
            key = 0xFFFFFFFFFFFFFFFFull;
        }
        s[i] = key;
    }
    __syncthreads();
    for (int k = 2; k <= SORTN; k <<= 1) {
        for (int j = k >> 1; j > 0; j >>= 1) {
            for (int p = threadIdx.x; p < SORTN / 2; p += blockDim.x) {
                int idx = ((p & ~(j - 1)) << 1) | (p & (j - 1));
                int partner = idx + j;
                bool up = ((idx & k) == 0);
                unsigned long long a = s[idx], c = s[partner];
                if ((a > c) == up) { s[idx] = c; s[partner] = a; }
            }
            __syncthreads();
        }
    }
    for (int i = threadIdx.x; i < KTOP; i += blockDim.x) {
        int local = (int)(s[i] & 0xFFFFFFFFu);
        g_topk[b * KTOP + i] = b * NPER + local;
    }
}

// ---------------- readout ------------------------------------------------------
__global__ void final_gemm_kernel(const float* __restrict__ W3, float* __restrict__ out) {
    int w = threadIdx.x >> 5, lane = threadIdx.x & 31;
    const int KTOT = KTOP * 128;
    int per = KTOT / gridDim.x;
    int k0 = blockIdx.x * per, k1 = k0 + per;
    float acc[NCLS];
    #pragma unroll
    for (int c = 0; c < NCLS; c++) acc[c] = 0.f;
    for (int k = k0 + lane; k < k1; k += 32) {
        int i = k >> 7, h = k & 127;
        int node = g_topk[w * KTOP + i];
        float x = g_h[(size_t)node * 128 + h];
        const float* wrow = &W3[(size_t)k * NCLS];
        #pragma unroll
        for (int c = 0; c < NCLS; c++) acc[c] += x * wrow[c];
    }
    #pragma unroll
    for (int c = 0; c < NCLS; c++) {
        float v = acc[c];
        #pragma unroll
        for (int o = 16; o > 0; o >>= 1) v += __shfl_down_sync(0xffffffffu, v, o);
        if (lane == 0) atomicAdd(&out[w * NCLS + c], v);
    }
}

// ---------------- launch ------------------------------------------------------
extern "C" void kernel_launch(void* const* d_in, const int* in_sizes, int n_in,
                              void* d_out, int out_size) {
    const float* features = (const float*)d_in[0];
    const int*   src      = (const int*)d_in[1];
    const int*   dst      = (const int*)d_in[2];
    const float* W1       = (const float*)d_in[3];
    const float* b1       = (const float*)d_in[4];
    const float* W2       = (const float*)d_in[5];
    const float* b2       = (const float*)d_in[6];
    const float* W3       = (const float*)d_in[7];
    const float* b3       = (const float*)d_in[8];
    float* out = (float*)d_out;

    const int smem_t1 = (64 * 128 + 32 * 64) * 4;    // 40 KB
    const int smem_t2 = (128 * 128 + 32 * 128) * 4;  // 80 KB
    cudaFuncSetAttribute(transform_kernel<64, 0, 0>,
        cudaFuncAttributeMaxDynamicSharedMemorySize, smem_t1);
    cudaFuncSetAttribute(transform_kernel<128, 1, 1>,
        cudaFuncAttributeMaxDynamicSharedMemorySize, smem_t2);
    cudaFuncSetAttribute(topk_kernel,
        cudaFuncAttributeMaxDynamicSharedMemorySize, SORTN * 8);

    // degree zeroing via memset nodes (capture-legal, device-to-device)
    void* deg_out_addr = nullptr;
    void* deg_in_addr = nullptr;
    cudaGetSymbolAddress(&deg_out_addr, g_deg_out);
    cudaGetSymbolAddress(&deg_in_addr, g_deg_in);
    cudaMemsetAsync(deg_out_addr, 0, NN * sizeof(int));
    cudaMemsetAsync(deg_in_addr, 0, NN * sizeof(int));

    // degrees + norms + CSR (by dst)
    degree_kernel<<<(EE + 255) / 256, 256>>>(src, dst);
    scan_block_sum_kernel<<<SCAN_BLOCKS, 1024>>>();
    scan_partials_kernel<<<1, 32>>>();
    scan_local_kernel<<<SCAN_BLOCKS, 1024>>>();   // also computes norms
    csr_fill_kernel<<<(EE + 255) / 256, 256>>>(src, dst);

    dim3 tblock(32, 8);
    // layer 1: scale -> aggregate(64-dim) -> GEMM(+norm_dst,bias,relu)
    scale_src_kernel<<<(NN * INDIM / 4 + 255) / 256, 256>>>(features);
    aggregate64_kernel<<<(NN * 32 + 255) / 256, 256>>>();
    transform_kernel<64, 0, 0><<<NN / 32, tblock, smem_t1>>>(W1, b1);
    // layer 2: GEMM(+norm_src) -> aggregate(128, +norm_dst,bias,relu)
    transform_kernel<128, 1, 1><<<NN / 32, tblock, smem_t2>>>(W2, nullptr);
    aggregate_kernel<<<(NN * 32 + 255) / 256, 256>>>(b2);

    // sort-pool (+fused out init) + readout
    topk_kernel<<<NBATCH, 1024, SORTN * 8>>>(b3, out);
    final_gemm_kernel<<<250, 256>>>(W3, out);
}

// round 8
// speedup vs baseline: 1.0147x; 1.0147x over previous
#include <cuda_runtime.h>
#include <cstdint>

#define NN    100000
#define EE    1600000
#define HIDD  128
#define INDIM 64
#define NBATCH 8
#define KTOP  5000
#define NPER  12500
#define NCLS  18
#define SORTN 16384
#define SCAN_BLOCKS 98   // ceil(100000 / 1024)

// ---------------- scratch (device globals; referenced ONLY from device code) --
__device__ float g_t[(size_t)NN * HIDD];        // transformed feats (layer-1 scaled / layer-2 xW)
__device__ float g_h[(size_t)NN * HIDD];        // layer output features
__device__ float g_agg[(size_t)NN * INDIM];     // layer-1 aggregated scaled features
__device__ float g_norm_src[NN];
__device__ float g_norm_dst[NN];
__device__ int   g_deg_out[NN];
__device__ int   g_deg_in[NN];
__device__ int   g_row_start[NN + 1];
__device__ int   g_cursor[NN];
__device__ int   g_csr_src[EE];
__device__ int   g_topk[NBATCH * KTOP];
__device__ int   g_scan_agg[SCAN_BLOCKS];
__device__ int   g_scan_flag[SCAN_BLOCKS];

// ---------------- degree (launch 1) -------------------------------------------
__global__ void degree_kernel(const int* __restrict__ src, const int* __restrict__ dst) {
    int e = blockIdx.x * blockDim.x + threadIdx.x;
    if (e < EE) {
        atomicAdd(&g_deg_out[src[e]], 1);
        atomicAdd(&g_deg_in[dst[e]], 1);
    }
}

// ---------------- single-kernel scan + norms (launch 2) ------------------------
// 98 blocks, all resident simultaneously (<=148 SMs) -> lookback cannot deadlock.
__global__ void scan_fused_kernel() {
    __shared__ int sh[1024];
    __shared__ int red[128];
    int tid = threadIdx.x, b = blockIdx.x;
    int i = b * 1024 + tid;
    int v = (i < NN) ? g_deg_in[i] : 0;

    // block aggregate
    sh[tid] = v;
    __syncthreads();
    #pragma unroll
    for (int off = 512; off > 0; off >>= 1) {
        if (tid < off) sh[tid] += sh[tid + off];
        __syncthreads();
    }
    int bsum = sh[0];
    __syncthreads();
    if (tid == 0) {
        *(volatile int*)&g_scan_agg[b] = bsum;
        __threadfence();
        *(volatile int*)&g_scan_flag[b] = 1;
    }

    // lookback: sum aggregates of all preceding blocks
    if (tid < 128) {
        int val = 0;
        if (tid < b) {
            while (*(volatile int*)&g_scan_flag[tid] == 0) {}
            val = *(volatile int*)&g_scan_agg[tid];
        }
        red[tid] = val;
    }
    __syncthreads();
    #pragma unroll
    for (int off = 64; off > 0; off >>= 1) {
        if (tid < off) red[tid] += red[tid + off];
        __syncthreads();
    }
    int offset = red[0];
    __syncthreads();

    // local inclusive scan
    sh[tid] = v;
    __syncthreads();
    #pragma unroll
    for (int o = 1; o < 1024; o <<= 1) {
        int add = (tid >= o) ? sh[tid - o] : 0;
        __syncthreads();
        sh[tid] += add;
        __syncthreads();
    }
    if (i < NN) {
        int excl = offset + sh[tid] - v;
        g_row_start[i] = excl;
        g_cursor[i] = excl;
        g_norm_dst[i] = rsqrtf((float)max(v, 1));
        g_norm_src[i] = rsqrtf((float)max(g_deg_out[i], 1));
    }
    if (b == SCAN_BLOCKS - 1 && tid == 0)
        g_row_start[NN] = offset + bsum;
}

// ---------------- csr fill + src scaling fused (launch 3) ----------------------
// EE == NN*INDIM/4 == 1.6M: one thread does one edge AND one float4 of scaling.
__global__ void csr_scale_kernel(const int* __restrict__ src,
                                 const int* __restrict__ dst,
                                 const float* __restrict__ x) {
    int e = blockIdx.x * blockDim.x + threadIdx.x;
    if (e < EE) {
        int d = dst[e];
        int pos = atomicAdd(&g_cursor[d], 1);
        g_csr_src[pos] = src[e];
        // scale part: same index range (NN*INDIM/4 == EE)
        int node = e >> 4;                    // 16 float4 per 64-float row
        float ns = g_norm_src[node];
        float4 v = *(const float4*)&x[e * 4];
        v.x *= ns; v.y *= ns; v.z *= ns; v.w *= ns;
        *(float4*)&g_t[e * 4] = v;
    }
}

// ---------------- 64-dim aggregate (launch 4 -> PROFILED) ----------------------
__global__ void aggregate64_kernel() {
    int gtid = blockIdx.x * blockDim.x + threadIdx.x;
    int node = gtid >> 5;
    int lane = gtid & 31;
    if (node >= NN) return;
    int s0 = g_row_start[node], s1 = g_row_start[node + 1];
    float2 acc0 = make_float2(0.f, 0.f);
    float2 acc1 = make_float2(0.f, 0.f);
    const float* tbase = (const float*)g_t;
    for (int base = s0; base < s1; base += 32) {
        int my = (base + lane < s1) ? g_csr_src[base + lane] : 0;
        int cnt = min(32, s1 - base);
        int t = 0;
        for (; t + 4 <= cnt; t += 4) {
            int sA = __shfl_sync(0xffffffffu, my, t);
            int sB = __shfl_sync(0xffffffffu, my, t + 1);
            int sC = __shfl_sync(0xffffffffu, my, t + 2);
            int sD = __shfl_sync(0xffffffffu, my, t + 3);
            float2 vA = *(const float2*)&tbase[(size_t)sA * 64 + lane * 2];
            float2 vB = *(const float2*)&tbase[(size_t)sB * 64 + lane * 2];
            float2 vC = *(const float2*)&tbase[(size_t)sC * 64 + lane * 2];
            float2 vD = *(const float2*)&tbase[(size_t)sD * 64 + lane * 2];
            acc0.x += vA.x; acc0.y += vA.y;
            acc1.x += vB.x; acc1.y += vB.y;
            acc0.x += vC.x; acc0.y += vC.y;
            acc1.x += vD.x; acc1.y += vD.y;
        }
        for (; t < cnt; t++) {
            int s = __shfl_sync(0xffffffffu, my, t);
            float2 v = *(const float2*)&tbase[(size_t)s * 64 + lane * 2];
            acc0.x += v.x; acc0.y += v.y;
        }
    }
    *(float2*)&g_agg[(size_t)node * 64 + lane * 2] =
        make_float2(acc0.x + acc1.x, acc0.y + acc1.y);
}

// ---------------- transform: 4 nodes x 4 cols per thread (scalar FMA) ---------
template <int KD, int SRC, int EPI>
__global__ void transform_kernel(const float* __restrict__ W,
                                 const float* __restrict__ bias) {
    extern __shared__ float sh[];
    float* Ws = sh;                  // KD*128
    float* xs = sh + KD * 128;       // 32*KD
    int tx = threadIdx.x, ty = threadIdx.y;
    int tid = ty * 32 + tx;          // 0..255
    for (int i = tid * 4; i < KD * 128; i += 256 * 4)
        *(float4*)&Ws[i] = *(const float4*)&W[i];
    int base = blockIdx.x * 32;
    const float* xin = (SRC == 0) ? (const float*)g_agg : (const float*)g_h;
    for (int i = tid * 4; i < 32 * KD; i += 256 * 4)
        *(float4*)&xs[i] = *(const float4*)&xin[(size_t)base * KD + i];
    __syncthreads();

    float4 acc0 = make_float4(0.f, 0.f, 0.f, 0.f);
    float4 acc1 = make_float4(0.f, 0.f, 0.f, 0.f);
    float4 acc2 = make_float4(0.f, 0.f, 0.f, 0.f);
    float4 acc3 = make_float4(0.f, 0.f, 0.f, 0.f);
    const float* x0p = &xs[(ty * 4 + 0) * KD];
    const float* x1p = &xs[(ty * 4 + 1) * KD];
    const float* x2p = &xs[(ty * 4 + 2) * KD];
    const float* x3p = &xs[(ty * 4 + 3) * KD];
    #pragma unroll 8
    for (int k = 0; k < KD; k++) {
        float4 wv = *(const float4*)&Ws[k * 128 + tx * 4];
        float x0 = x0p[k], x1 = x1p[k], x2 = x2p[k], x3 = x3p[k];
        acc0.x += x0 * wv.x; acc0.y += x0 * wv.y; acc0.z += x0 * wv.z; acc0.w += x0 * wv.w;
        acc1.x += x1 * wv.x; acc1.y += x1 * wv.y; acc1.z += x1 * wv.z; acc1.w += x1 * wv.w;
        acc2.x += x2 * wv.x; acc2.y += x2 * wv.y; acc2.z += x2 * wv.z; acc2.w += x2 * wv.w;
        acc3.x += x3 * wv.x; acc3.y += x3 * wv.y; acc3.z += x3 * wv.z; acc3.w += x3 * wv.w;
    }

    int n0 = base + ty * 4;
    float4 accs[4] = {acc0, acc1, acc2, acc3};
    if (EPI == 0) {
        float4 b = *(const float4*)&bias[tx * 4];
        #pragma unroll
        for (int i = 0; i < 4; i++) {
            float nd = g_norm_dst[n0 + i];
            float4 a = accs[i];
            float4 r;
            r.x = fmaxf(a.x * nd + b.x, 0.f);
            r.y = fmaxf(a.y * nd + b.y, 0.f);
            r.z = fmaxf(a.z * nd + b.z, 0.f);
            r.w = fmaxf(a.w * nd + b.w, 0.f);
            *(float4*)&g_h[(size_t)(n0 + i) * 128 + tx * 4] = r;
        }
    } else {
        #pragma unroll
        for (int i = 0; i < 4; i++) {
            float ns = g_norm_src[n0 + i];
            float4 a = accs[i];
            a.x *= ns; a.y *= ns; a.z *= ns; a.w *= ns;
            *(float4*)&g_t[(size_t)(n0 + i) * 128 + tx * 4] = a;
        }
    }
}

// ---------------- 128-dim aggregate (layer 2) ---------------------------------
__global__ void aggregate_kernel(const float* __restrict__ bias) {
    int gtid = blockIdx.x * blockDim.x + threadIdx.x;
    int node = gtid >> 5;
    int lane = gtid & 31;
    if (node >= NN) return;
    int s0 = g_row_start[node], s1 = g_row_start[node + 1];
    float4 acc0 = make_float4(0.f, 0.f, 0.f, 0.f);
    float4 acc1 = make_float4(0.f, 0.f, 0.f, 0.f);
    const float* tbase = (const float*)g_t;
    for (int base = s0; base < s1; base += 32) {
        int my = (base + lane < s1) ? g_csr_src[base + lane] : 0;
        int cnt = min(32, s1 - base);
        int t = 0;
        for (; t + 4 <= cnt; t += 4) {
            int sA = __shfl_sync(0xffffffffu, my, t);
            int sB = __shfl_sync(0xffffffffu, my, t + 1);
            int sC = __shfl_sync(0xffffffffu, my, t + 2);
            int sD = __shfl_sync(0xffffffffu, my, t + 3);
            float4 vA = *(const float4*)&tbase[(size_t)sA * 128 + lane * 4];
            float4 vB = *(const float4*)&tbase[(size_t)sB * 128 + lane * 4];
            float4 vC = *(const float4*)&tbase[(size_t)sC * 128 + lane * 4];
            float4 vD = *(const float4*)&tbase[(size_t)sD * 128 + lane * 4];
            acc0.x += vA.x; acc0.y += vA.y; acc0.z += vA.z; acc0.w += vA.w;
            acc1.x += vB.x; acc1.y += vB.y; acc1.z += vB.z; acc1.w += vB.w;
            acc0.x += vC.x; acc0.y += vC.y; acc0.z += vC.z; acc0.w += vC.w;
            acc1.x += vD.x; acc1.y += vD.y; acc1.z += vD.z; acc1.w += vD.w;
        }
        for (; t < cnt; t++) {
            int s = __shfl_sync(0xffffffffu, my, t);
            float4 v = *(const float4*)&tbase[(size_t)s * 128 + lane * 4];
            acc0.x += v.x; acc0.y += v.y; acc0.z += v.z; acc0.w += v.w;
        }
    }
    float nd = g_norm_dst[node];
    float4 b = *(const float4*)&bias[lane * 4];
    float4 r;
    r.x = fmaxf((acc0.x + acc1.x) * nd + b.x, 0.f);
    r.y = fmaxf((acc0.y + acc1.y) * nd + b.y, 0.f);
    r.z = fmaxf((acc0.z + acc1.z) * nd + b.z, 0.f);
    r.w = fmaxf((acc0.w + acc1.w) * nd + b.w, 0.f);
    *(float4*)&g_h[(size_t)node * 128 + lane * 4] = r;
}

// ---------------- top-K + fused out init --------------------------------------
__global__ void topk_kernel(const float* __restrict__ b3, float* __restrict__ out) {
    extern __shared__ unsigned long long s[];
    int b = blockIdx.x;
    if (b == 0 && threadIdx.x < NBATCH * NCLS)
        out[threadIdx.x] = b3[threadIdx.x % NCLS];
    for (int i = threadIdx.x; i < SORTN; i += blockDim.x) {
        unsigned long long key;
        if (i < NPER) {
            float f = g_h[((size_t)(b * NPER + i)) * 128 + 127];
            unsigned bits = __float_as_uint(f);
            unsigned m = ((int)bits < 0) ? ~bits : (bits ^ 0x80000000u);
            key = (((unsigned long long)(~m)) << 32) | (unsigned)i;
        } else {
            key = 0xFFFFFFFFFFFFFFFFull;
        }
        s[i] = key;
    }
    __syncthreads();
    for (int k = 2; k <= SORTN; k <<= 1) {
        for (int j = k >> 1; j > 0; j >>= 1) {
            for (int p = threadIdx.x; p < SORTN / 2; p += blockDim.x) {
                int idx = ((p & ~(j - 1)) << 1) | (p & (j - 1));
                int partner = idx + j;
                bool up = ((idx & k) == 0);
                unsigned long long a = s[idx], c = s[partner];
                if ((a > c) == up) { s[idx] = c; s[partner] = a; }
            }
            __syncthreads();
        }
    }
    for (int i = threadIdx.x; i < KTOP; i += blockDim.x) {
        int local = (int)(s[i] & 0xFFFFFFFFu);
        g_topk[b * KTOP + i] = b * NPER + local;
    }
}

// ---------------- readout ------------------------------------------------------
__global__ void final_gemm_kernel(const float* __restrict__ W3, float* __restrict__ out) {
    int w = threadIdx.x >> 5, lane = threadIdx.x & 31;
    const int KTOT = KTOP * 128;
    int per = KTOT / gridDim.x;
    int k0 = blockIdx.x * per, k1 = k0 + per;
    float acc[NCLS];
    #pragma unroll
    for (int c = 0; c < NCLS; c++) acc[c] = 0.f;
    for (int k = k0 + lane; k < k1; k += 32) {
        int i = k >> 7, h = k & 127;
        int node = g_topk[w * KTOP + i];
        float x = g_h[(size_t)node * 128 + h];
        const float* wrow = &W3[(size_t)k * NCLS];
        #pragma unroll
        for (int c = 0; c < NCLS; c++) acc[c] += x * wrow[c];
    }
    #pragma unroll
    for (int c = 0; c < NCLS; c++) {
        float v = acc[c];
        #pragma unroll
        for (int o = 16; o > 0; o >>= 1) v += __shfl_down_sync(0xffffffffu, v, o);
        if (lane == 0) atomicAdd(&out[w * NCLS + c], v);
    }
}

// ---------------- launch ------------------------------------------------------
extern "C" void kernel_launch(void* const* d_in, const int* in_sizes, int n_in,
                              void* d_out, int out_size) {
    const float* features = (const float*)d_in[0];
    const int*   src      = (const int*)d_in[1];
    const int*   dst      = (const int*)d_in[2];
    const float* W1       = (const float*)d_in[3];
    const float* b1       = (const float*)d_in[4];
    const float* W2       = (const float*)d_in[5];
    const float* b2       = (const float*)d_in[6];
    const float* W3       = (const float*)d_in[7];
    const float* b3       = (const float*)d_in[8];
    float* out = (float*)d_out;

    const int smem_t1 = (64 * 128 + 32 * 64) * 4;    // 40 KB
    const int smem_t2 = (128 * 128 + 32 * 128) * 4;  // 80 KB
    cudaFuncSetAttribute(transform_kernel<64, 0, 0>,
        cudaFuncAttributeMaxDynamicSharedMemorySize, smem_t1);
    cudaFuncSetAttribute(transform_kernel<128, 1, 1>,
        cudaFuncAttributeMaxDynamicSharedMemorySize, smem_t2);
    cudaFuncSetAttribute(topk_kernel,
        cudaFuncAttributeMaxDynamicSharedMemorySize, SORTN * 8);

    // zero degree arrays + scan flags via memset nodes (not kernel launches)
    void* deg_out_addr = nullptr;
    void* deg_in_addr = nullptr;
    void* flag_addr = nullptr;
    cudaGetSymbolAddress(&deg_out_addr, g_deg_out);
    cudaGetSymbolAddress(&deg_in_addr, g_deg_in);
    cudaGetSymbolAddress(&flag_addr, g_scan_flag);
    cudaMemsetAsync(deg_out_addr, 0, NN * sizeof(int));
    cudaMemsetAsync(deg_in_addr, 0, NN * sizeof(int));
    cudaMemsetAsync(flag_addr, 0, SCAN_BLOCKS * sizeof(int));

    // launch 1-3: degree, fused scan(+norms), csr fill + src scaling
    degree_kernel<<<(EE + 255) / 256, 256>>>(src, dst);
    scan_fused_kernel<<<SCAN_BLOCKS, 1024>>>();
    csr_scale_kernel<<<(EE + 255) / 256, 256>>>(src, dst, features);

    // launch 4 (PROFILED): 64-dim gather aggregate
    aggregate64_kernel<<<(NN * 32 + 255) / 256, 256>>>();

    dim3 tblock(32, 8);
    // layer 1 GEMM(+norm_dst,bias,relu); layer 2 GEMM(+norm_src) -> aggregate
    transform_kernel<64, 0, 0><<<NN / 32, tblock, smem_t1>>>(W1, b1);
    transform_kernel<128, 1, 1><<<NN / 32, tblock, smem_t2>>>(W2, nullptr);
    aggregate_kernel<<<(NN * 32 + 255) / 256, 256>>>(b2);

    // sort-pool (+fused out init) + readout
    topk_kernel<<<NBATCH, 1024, SORTN * 8>>>(b3, out);
    final_gemm_kernel<<<250, 256>>>(W3, out);
}